// round 9
// baseline (speedup 1.0000x reference)
#include <cuda_runtime.h>
#include <cuda_bf16.h>
#include <cstdint>
#include <math.h>

#define PP 4
#define BB 128
#define DD 512
#define NN 32768
#define KK 10
#define TEMP_INV 2.0f
#define SCALEC 10.0f
#define KL_WEIGHT (59.0f/120.0f)

// ================= scratch (16B-aligned: we float4-cast these) =================
__device__ __align__(16) float g_img[PP*BB*DD];
__device__ __align__(16) float g_txt[PP*BB*DD];
__device__ __align__(16) float g_fn2[PP*BB];
__device__ __align__(16) float g_negmask[NN];     // 0 = keep, 1 = masked (memset-0 friendly)
__device__ __align__(16) float g_negsum[PP*BB];
__device__ __align__(16) float g_lp[PP];
__device__ __align__(16) float g_klp[PP];
__device__ __align__(16) __nv_bfloat16 g_featbf[PP*BB*DD];   // raw feature in bf16
__device__ int g_done;

// ================= helpers =================
__device__ __forceinline__ void cp16(uint32_t dst, const void* src) {
    asm volatile("cp.async.cg.shared.global [%0], [%1], 16;" :: "r"(dst), "l"(src));
}
#define CP_COMMIT() asm volatile("cp.async.commit_group;" ::: "memory")
#define CP_WAIT1()  asm volatile("cp.async.wait_group 1;" ::: "memory")

__device__ __forceinline__ uint32_t smem_u32(const void* p) {
    uint32_t a;
    asm("{ .reg .u64 t; cvta.to.shared.u64 t, %1; cvt.u32.u64 %0, t; }" : "=r"(a) : "l"(p));
    return a;
}
__device__ __forceinline__ uint32_t pack_bf16(float lo, float hi) {
    uint32_t u;
    asm("cvt.rn.bf16x2.f32 %0, %1, %2;" : "=r"(u) : "f"(hi), "f"(lo));  // d.hi=%1, d.lo=%2
    return u;
}
__device__ __forceinline__ void sts128(uint32_t addr, uint32_t a, uint32_t b,
                                       uint32_t c, uint32_t d) {
    asm volatile("st.shared.v4.b32 [%0], {%1,%2,%3,%4};"
                 :: "r"(addr), "r"(a), "r"(b), "r"(c), "r"(d));
}
__device__ __forceinline__ void mma_bf16(float* d, const uint32_t* a, const uint32_t* b) {
    asm volatile(
        "mma.sync.aligned.m16n8k16.row.col.f32.bf16.bf16.f32 "
        "{%0,%1,%2,%3}, {%4,%5,%6,%7}, {%8,%9}, {%0,%1,%2,%3};"
        : "+f"(d[0]), "+f"(d[1]), "+f"(d[2]), "+f"(d[3])
        : "r"(a[0]), "r"(a[1]), "r"(a[2]), "r"(a[3]), "r"(b[0]), "r"(b[1]));
}

// ================= kernel A: scatter + normalize + bf16 feature =================
// block 0: scatter mask=1 at masked indices (arrays pre-zeroed by memset).
// blocks 1..512: normalize feature/text row pb = bid-1, fn2, bf16 feature copy.
__global__ void __launch_bounds__(128) k_pre(const float* __restrict__ feature,
                                             const float* __restrict__ text,
                                             const int* __restrict__ cross,
                                             const int* __restrict__ pos) {
    int tid = threadIdx.x;
    if (blockIdx.x == 0) {
        for (int i = tid; i < BB*KK; i += 128) g_negmask[cross[i]] = 1.0f;
        for (int i = tid; i < BB; i += 128) g_negmask[pos[i]] = 1.0f;
        return;
    }
    __shared__ float s4[4];
    int pb = blockIdx.x - 1;
    int p = pb >> 7, b = pb & 127;

    float4 f = ((const float4*)(feature + (size_t)pb * DD))[tid];
    // bf16 copy of RAW feature
    ((uint2*)(g_featbf + (size_t)pb * DD))[tid] =
        make_uint2(pack_bf16(f.x, f.y), pack_bf16(f.z, f.w));
    float ss = f.x*f.x + f.y*f.y + f.z*f.z + f.w*f.w;
    #pragma unroll
    for (int o = 16; o; o >>= 1) ss += __shfl_xor_sync(~0u, ss, o);
    if ((tid & 31) == 0) s4[tid >> 5] = ss;
    __syncthreads();
    ss = s4[0] + s4[1] + s4[2] + s4[3];
    if (tid == 0) g_fn2[pb] = ss;
    float inv = 1.0f / fmaxf(sqrtf(ss), 1e-12f);
    ((float4*)(g_img + (size_t)pb * DD))[tid] =
        make_float4(f.x*inv, f.y*inv, f.z*inv, f.w*inv);
    __syncthreads();

    float4 t = ((const float4*)(text + ((size_t)b * PP + p) * DD))[tid];
    float ts = t.x*t.x + t.y*t.y + t.z*t.z + t.w*t.w;
    #pragma unroll
    for (int o = 16; o; o >>= 1) ts += __shfl_xor_sync(~0u, ts, o);
    if ((tid & 31) == 0) s4[tid >> 5] = ts;
    __syncthreads();
    ts = s4[0] + s4[1] + s4[2] + s4[3];
    float tinv = 1.0f / fmaxf(sqrtf(ts), 1e-12f);
    ((float4*)(g_txt + (size_t)pb * DD))[tid] =
        make_float4(t.x*tinv, t.y*tinv, t.z*tinv, t.w*tinv);
}

// ================= neg term: bf16 mma.sync GEMM =================
// Block (n0 = bx*128, p = by): D[128 b][128 n] = feature . centers^T (bf16 in, f32 acc)
// 8 warps, warp tile 64x32 via m16n8k16. K=512 in 16 chunks of 32.
// A (bf16 feature) via 3-stage cp.async. B (fp32 centers) via reg LDG 2 chunks
// ahead -> cvt bf16 -> STS, 2 stages. cn2 exact fp32 from the LDG registers.
#define APITCH 80                 // bytes per smem row (40 bf16): conflict-free frags
#define A_STAGE 10240             // 128*80
#define B_STAGE 10240
#define NEG_SMEM (3*A_STAGE + 2*B_STAGE)   // 51200

__device__ __forceinline__ void load_A(const __nv_bfloat16* __restrict__ Abf,
                                       uint32_t base, int c, int stage, int tid) {
    int k0 = c * 32;
    uint32_t sA = base + (uint32_t)stage * A_STAGE;
    #pragma unroll
    for (int i = 0; i < 2; i++) {
        int q = i * 256 + tid;        // 512 granules of 16B
        int row = q >> 2;
        int g = q & 3;
        cp16(sA + (uint32_t)(row * APITCH + g * 16), Abf + (size_t)row * DD + k0 + g * 8);
    }
    CP_COMMIT();
}

__global__ void __launch_bounds__(256, 2)
k_neg(const float* __restrict__ centers) {
    extern __shared__ __align__(16) char dsm[];
    __shared__ float s_cn2[128];
    __shared__ float s_fn2[128];
    __shared__ float s_keep[128];
    __shared__ float s_bsum[128];

    uint32_t base = smem_u32(dsm);
    uint32_t baseB = base + 3 * A_STAGE;
    int tid = threadIdx.x;
    int wid = tid >> 5, lane = tid & 31;
    int row4 = lane >> 2, col4 = lane & 3;
    int warp_m = wid >> 2, warp_n = wid & 3;
    int mbase = warp_m * 64, nbase = warp_n * 32;
    int p = blockIdx.y;
    int n0 = blockIdx.x * 128;

    if (tid < 128) {
        s_keep[tid] = 1.0f - g_negmask[n0 + tid];
        s_fn2[tid] = g_fn2[p * BB + tid];
        s_bsum[tid] = 0.0f;
    }

    const __nv_bfloat16* Abf = g_featbf + (size_t)p * BB * DD;
    const float* B = centers + ((size_t)p * NN + n0) * DD;

    // B-load role: thread t -> row r, k-segment (16 floats)
    int brow = tid >> 1, bseg = tid & 1;
    const float* Brow = B + (size_t)brow * DD + bseg * 16;
    uint32_t bsts_base = baseB + (uint32_t)(brow * APITCH + ((bseg ^ (brow & 1)) * 32));

    float acc[4][4][4];
    #pragma unroll
    for (int i = 0; i < 4; i++)
        #pragma unroll
        for (int j = 0; j < 4; j++)
            #pragma unroll
            for (int r = 0; r < 4; r++) acc[i][j][r] = 0.0f;
    float cn2acc = 0.0f;
    float4 breg[4];

    // ---- prologue ----
    #pragma unroll
    for (int i = 0; i < 4; i++) breg[i] = ((const float4*)Brow)[i];            // B0
    #pragma unroll
    for (int i = 0; i < 4; i++)
        cn2acc += breg[i].x*breg[i].x + breg[i].y*breg[i].y + breg[i].z*breg[i].z + breg[i].w*breg[i].w;
    {   // cvt + STS B0 -> stage 0
        uint32_t u[8];
        #pragma unroll
        for (int i = 0; i < 4; i++) {
            u[2*i]   = pack_bf16(breg[i].x, breg[i].y);
            u[2*i+1] = pack_bf16(breg[i].z, breg[i].w);
        }
        sts128(bsts_base, u[0], u[1], u[2], u[3]);
        sts128(bsts_base + 16, u[4], u[5], u[6], u[7]);
    }
    load_A(Abf, base, 0, 0, tid);
    load_A(Abf, base, 1, 1, tid);
    #pragma unroll
    for (int i = 0; i < 4; i++) breg[i] = ((const float4*)(Brow + 32))[i];     // B1
    #pragma unroll
    for (int i = 0; i < 4; i++)
        cn2acc += breg[i].x*breg[i].x + breg[i].y*breg[i].y + breg[i].z*breg[i].z + breg[i].w*breg[i].w;

    for (int c = 0; c < 16; c++) {
        CP_WAIT1();                 // A_c landed
        __syncthreads();            // all STS/cp.async of chunk c visible; old stages drained

        if (c + 2 < 16) load_A(Abf, base, c + 2, (c + 2) % 3, tid);
        else            CP_COMMIT();

        if (c + 1 < 16) {           // cvt + STS B_{c+1} into stage (c+1)&1
            uint32_t u[8];
            #pragma unroll
            for (int i = 0; i < 4; i++) {
                u[2*i]   = pack_bf16(breg[i].x, breg[i].y);
                u[2*i+1] = pack_bf16(breg[i].z, breg[i].w);
            }
            uint32_t dst = bsts_base + (uint32_t)(((c + 1) & 1) * B_STAGE);
            sts128(dst, u[0], u[1], u[2], u[3]);
            sts128(dst + 16, u[4], u[5], u[6], u[7]);
        }
        if (c + 2 < 16) {           // LDG B_{c+2} (2 chunks of latency slack)
            const float* src = Brow + (c + 2) * 32;
            #pragma unroll
            for (int i = 0; i < 4; i++) breg[i] = ((const float4*)src)[i];
            #pragma unroll
            for (int i = 0; i < 4; i++)
                cn2acc += breg[i].x*breg[i].x + breg[i].y*breg[i].y + breg[i].z*breg[i].z + breg[i].w*breg[i].w;
        }

        const char* sA = dsm + (size_t)(c % 3) * A_STAGE;
        const char* sB = dsm + 3 * A_STAGE + (size_t)(c & 1) * B_STAGE;

        #pragma unroll
        for (int kk = 0; kk < 2; kk++) {
            uint32_t afr[4][4];
            #pragma unroll
            for (int i = 0; i < 4; i++) {
                int row = mbase + i * 16 + row4;
                const char* Ar = sA + row * APITCH + kk * 32 + col4 * 4;
                afr[i][0] = *(const uint32_t*)(Ar);
                afr[i][1] = *(const uint32_t*)(Ar + 8 * APITCH);
                afr[i][2] = *(const uint32_t*)(Ar + 16);
                afr[i][3] = *(const uint32_t*)(Ar + 8 * APITCH + 16);
            }
            uint32_t bfr[4][2];
            #pragma unroll
            for (int j = 0; j < 4; j++) {
                int n = nbase + j * 8 + row4;
                const char* Br = sB + n * APITCH + ((kk ^ (n & 1)) * 32) + col4 * 4;
                bfr[j][0] = *(const uint32_t*)(Br);
                bfr[j][1] = *(const uint32_t*)(Br + 16);
            }
            #pragma unroll
            for (int i = 0; i < 4; i++)
                #pragma unroll
                for (int j = 0; j < 4; j++)
                    mma_bf16(acc[i][j], afr[i], bfr[j]);
        }
    }

    // exact fp32 cn2: combine the two half-row partials
    cn2acc += __shfl_xor_sync(~0u, cn2acc, 1);
    if ((tid & 1) == 0) s_cn2[brow] = cn2acc;
    __syncthreads();

    #pragma unroll
    for (int i = 0; i < 4; i++) {
        #pragma unroll
        for (int half = 0; half < 2; half++) {
            int b = mbase + i * 16 + row4 + half * 8;
            float fn2v = s_fn2[b];
            float s = 0.0f;
            #pragma unroll
            for (int j = 0; j < 4; j++) {
                #pragma unroll
                for (int q = 0; q < 2; q++) {
                    int n = nbase + j * 8 + col4 * 2 + q;
                    float v = acc[i][j][half * 2 + q];
                    float pd2 = fn2v + s_cn2[n] - 2.0f * v;
                    float dist = sqrtf(fmaxf(pd2, 1e-12f));
                    s += __expf(-SCALEC * dist) * s_keep[n];
                }
            }
            atomicAdd(&s_bsum[b], s);
        }
    }
    __syncthreads();
    if (tid < 128) atomicAdd(&g_negsum[p * BB + tid], s_bsum[tid]);
}

// ================= tail: pos + align + final (one launch) =================
__global__ void __launch_bounds__(256) k_tail(const float* __restrict__ feature,
                                              const float* __restrict__ centers,
                                              const int* __restrict__ cross,
                                              const int* __restrict__ vid,
                                              float* __restrict__ out) {
    int tid = threadIdx.x;
    int bid = blockIdx.x;

    if (bid < 512) {
        // -------- positive term for pb = bid (exact fp32) --------
        __shared__ __align__(16) float s_f[DD];
        __shared__ float s_e[KK];
        int pb = bid; int p = pb >> 7, b = pb & 127;
        if (tid < 128) ((float4*)s_f)[tid] = ((const float4*)(feature + (size_t)pb * DD))[tid];
        __syncthreads();
        int w = tid >> 5, lane = tid & 31;
        float fn2 = g_fn2[pb];
        for (int k = w; k < KK; k += 8) {
            int n = cross[b * KK + k];
            const float4* c4 = (const float4*)(centers + ((size_t)p * NN + n) * DD);
            float dot = 0.0f, cn2 = 0.0f;
            for (int i = lane; i < DD/4; i += 32) {
                float4 c = c4[i];
                float4 f = ((const float4*)s_f)[i];
                dot += f.x*c.x + f.y*c.y + f.z*c.z + f.w*c.w;
                cn2 += c.x*c.x + c.y*c.y + c.z*c.z + c.w*c.w;
            }
            #pragma unroll
            for (int o = 16; o; o >>= 1) {
                dot += __shfl_xor_sync(~0u, dot, o);
                cn2 += __shfl_xor_sync(~0u, cn2, o);
            }
            if (lane == 0) {
                float dist = sqrtf(fmaxf(fn2 + cn2 - 2.0f * dot, 1e-12f));
                s_e[k] = expf(-SCALEC * dist);
            }
        }
        __syncthreads();
        if (tid == 0) {
            float se = 0.0f;
            for (int k = 0; k < KK; k++) se += s_e[k];
            atomicAdd(&g_lp[p], logf(g_negsum[pb]) - logf(se));
        }
    } else {
        // -------- align tile: colm/valid provably all-true (diag cos/TEMP = 2 > 0.7) --------
        __shared__ __align__(16) float rows[8][512];
        __shared__ __align__(16) float chunk[128][36];
        __shared__ __align__(16) float sim[2][8][128];
        int ab = bid - 512;
        int p = ab >> 4;
        int r0 = (ab & 15) * 8;
        int c = tid & 127, rh = tid >> 7;

        for (int src = 0; src < 2; src++) {
            const float* X = (src ? g_txt : g_img) + (size_t)p * BB * DD;
            __syncthreads();
            for (int i = tid; i < 8 * 128; i += 256) {
                int r = i >> 7, g = i & 127;
                ((float4*)rows[r])[g] = ((const float4*)(X + (size_t)(r0 + r) * DD))[g];
            }
            float acc[4] = {0.f, 0.f, 0.f, 0.f};
            for (int d0 = 0; d0 < 512; d0 += 32) {
                __syncthreads();
                for (int i = tid; i < 1024; i += 256) {
                    int r = i >> 3, g = i & 7;
                    float4 v = ((const float4*)(X + (size_t)r * DD + d0))[g];
                    chunk[r][g*4+0] = v.x; chunk[r][g*4+1] = v.y;
                    chunk[r][g*4+2] = v.z; chunk[r][g*4+3] = v.w;
                }
                __syncthreads();
                #pragma unroll
                for (int dg = 0; dg < 8; dg++) {
                    float4 cv = *(const float4*)&chunk[c][dg * 4];
                    #pragma unroll
                    for (int i = 0; i < 4; i++) {
                        float4 rv = *(const float4*)&rows[rh * 4 + i][d0 + dg * 4];
                        acc[i] += rv.x*cv.x + rv.y*cv.y + rv.z*cv.z + rv.w*cv.w;
                    }
                }
            }
            #pragma unroll
            for (int i = 0; i < 4; i++) sim[src][rh * 4 + i][c] = acc[i] * TEMP_INV;
        }
        __syncthreads();

        int w = tid >> 5, lane = tid & 31;
        float li[4], lt[4];
        #pragma unroll
        for (int j = 0; j < 4; j++) {
            li[j] = sim[0][w][lane + 32 * j];
            lt[j] = sim[1][w][lane + 32 * j];
        }
        float mi = fmaxf(fmaxf(li[0], li[1]), fmaxf(li[2], li[3]));
        float mt = fmaxf(fmaxf(lt[0], lt[1]), fmaxf(lt[2], lt[3]));
        #pragma unroll
        for (int o = 16; o; o >>= 1) {
            mi = fmaxf(mi, __shfl_xor_sync(~0u, mi, o));
            mt = fmaxf(mt, __shfl_xor_sync(~0u, mt, o));
        }
        float si = 0.f, stt = 0.f;
        #pragma unroll
        for (int j = 0; j < 4; j++) { si += expf(li[j] - mi); stt += expf(lt[j] - mt); }
        #pragma unroll
        for (int o = 16; o; o >>= 1) {
            si += __shfl_xor_sync(~0u, si, o);
            stt += __shfl_xor_sync(~0u, stt, o);
        }
        float Li = mi + logf(si), Lt = mt + logf(stt);
        float kl = 0.f;
        #pragma unroll
        for (int j = 0; j < 4; j++) {
            float lpi = li[j] - Li, lpt = lt[j] - Lt;
            kl += expf(lpt) * (lpt - lpi) + expf(lpi) * (lpi - lpt);
        }
        #pragma unroll
        for (int o = 16; o; o >>= 1) kl += __shfl_xor_sync(~0u, kl, o);
        if (lane == 0) atomicAdd(&g_klp[p], kl);
    }

    // -------- last-block-done: finalize --------
    __shared__ int s_last;
    __syncthreads();
    if (tid == 0) {
        __threadfence();
        s_last = (atomicAdd(&g_done, 1) == 575);
    }
    __syncthreads();
    if (s_last) {
        __threadfence();
        for (int i = tid; i < BB*KK; i += 256) out[3 + i] = (float)vid[__ldcg(&cross[i])];
        if (tid == 0) {
            float contr = 0.0f;
            for (int p = 0; p < PP; p++) {
                float lp = __ldcg(&g_lp[p]) / (float)BB;
                if (isnan(lp)) lp = 0.0f;
                contr += lp;
            }
            contr /= (float)PP;
            float align = 0.0f;
            for (int p = 0; p < PP; p++) align += 0.5f * __ldcg(&g_klp[p]) / (float)BB;
            out[0] = contr + KL_WEIGHT * align;
            out[1] = contr;
            out[2] = align;
        }
    }
}

// ================= launch =================
extern "C" void kernel_launch(void* const* d_in, const int* in_sizes, int n_in,
                              void* d_out, int out_size) {
    const float* feature = (const float*)d_in[0];
    const float* text    = (const float*)d_in[1];
    const float* centers = (const float*)d_in[2];
    const int*   positn  = (const int*)d_in[3];
    const int*   cross   = (const int*)d_in[4];
    const int*   vid     = (const int*)d_in[5];
    float* out = (float*)d_out;

    cudaFuncSetAttribute(k_neg, cudaFuncAttributeMaxDynamicSharedMemorySize, NEG_SMEM);

    void *pm, *ps, *pl, *pk, *pd;
    cudaGetSymbolAddress(&pm, g_negmask);
    cudaGetSymbolAddress(&ps, g_negsum);
    cudaGetSymbolAddress(&pl, g_lp);
    cudaGetSymbolAddress(&pk, g_klp);
    cudaGetSymbolAddress(&pd, g_done);
    cudaMemsetAsync(pm, 0, NN * sizeof(float));
    cudaMemsetAsync(ps, 0, PP * BB * sizeof(float));
    cudaMemsetAsync(pl, 0, PP * sizeof(float));
    cudaMemsetAsync(pk, 0, PP * sizeof(float));
    cudaMemsetAsync(pd, 0, sizeof(int));

    k_pre<<<513, 128>>>(feature, text, cross, positn);
    k_neg<<<dim3(NN/128, PP), 256, NEG_SMEM>>>(centers);
    k_tail<<<576, 256>>>(feature, centers, cross, vid, out);
}

// round 12
// speedup vs baseline: 1.1740x; 1.1740x over previous
#include <cuda_runtime.h>
#include <cuda_bf16.h>
#include <cstdint>
#include <math.h>

#define PP 4
#define BB 128
#define DD 512
#define NN 32768
#define KK 10
#define TEMP_INV 2.0f
#define SCALEC 10.0f
#define KL_WEIGHT (59.0f/120.0f)

// ================= scratch (16B-aligned: we float4-cast these) =================
__device__ __align__(16) float g_img[PP*BB*DD];
__device__ __align__(16) float g_txt[PP*BB*DD];
__device__ __align__(16) float g_fn2[PP*BB];
__device__ __align__(16) float g_negmask[NN];     // 0 = keep, 1 = masked (memset-0 friendly)
__device__ __align__(16) float g_negsum[PP*BB];
__device__ __align__(16) float g_lp[PP];
__device__ __align__(16) float g_klp[PP];
__device__ __align__(16) __nv_bfloat16 g_featbf[PP*BB*DD];   // raw feature in bf16
__device__ int g_done;

// ================= helpers =================
__device__ __forceinline__ void cp16(uint32_t dst, const void* src) {
    asm volatile("cp.async.cg.shared.global [%0], [%1], 16;" :: "r"(dst), "l"(src));
}
#define CP_COMMIT() asm volatile("cp.async.commit_group;" ::: "memory")
#define CP_WAIT1()  asm volatile("cp.async.wait_group 1;" ::: "memory")
#define CP_WAIT0()  asm volatile("cp.async.wait_group 0;" ::: "memory")

__device__ __forceinline__ uint32_t smem_u32(const void* p) {
    uint32_t a;
    asm("{ .reg .u64 t; cvta.to.shared.u64 t, %1; cvt.u32.u64 %0, t; }" : "=r"(a) : "l"(p));
    return a;
}
__device__ __forceinline__ uint32_t pack_bf16(float lo, float hi) {
    uint32_t u;
    asm("cvt.rn.bf16x2.f32 %0, %1, %2;" : "=r"(u) : "f"(hi), "f"(lo));  // d.hi=%1, d.lo=%2
    return u;
}
__device__ __forceinline__ void sts128(uint32_t addr, uint32_t a, uint32_t b,
                                       uint32_t c, uint32_t d) {
    asm volatile("st.shared.v4.b32 [%0], {%1,%2,%3,%4};"
                 :: "r"(addr), "r"(a), "r"(b), "r"(c), "r"(d));
}
__device__ __forceinline__ void mma_bf16(float* d, const uint32_t* a, const uint32_t* b) {
    asm volatile(
        "mma.sync.aligned.m16n8k16.row.col.f32.bf16.bf16.f32 "
        "{%0,%1,%2,%3}, {%4,%5,%6,%7}, {%8,%9}, {%0,%1,%2,%3};"
        : "+f"(d[0]), "+f"(d[1]), "+f"(d[2]), "+f"(d[3])
        : "r"(a[0]), "r"(a[1]), "r"(a[2]), "r"(a[3]), "r"(b[0]), "r"(b[1]));
}

// ================= kernel A: scatter + normalize + bf16 feature =================
__global__ void __launch_bounds__(128) k_pre(const float* __restrict__ feature,
                                             const float* __restrict__ text,
                                             const int* __restrict__ cross,
                                             const int* __restrict__ pos) {
    int tid = threadIdx.x;
    if (blockIdx.x == 0) {
        for (int i = tid; i < BB*KK; i += 128) g_negmask[cross[i]] = 1.0f;
        for (int i = tid; i < BB; i += 128) g_negmask[pos[i]] = 1.0f;
        return;
    }
    __shared__ float s4[4];
    int pb = blockIdx.x - 1;
    int p = pb >> 7, b = pb & 127;

    float4 f = ((const float4*)(feature + (size_t)pb * DD))[tid];
    ((uint2*)(g_featbf + (size_t)pb * DD))[tid] =
        make_uint2(pack_bf16(f.x, f.y), pack_bf16(f.z, f.w));
    float ss = f.x*f.x + f.y*f.y + f.z*f.z + f.w*f.w;
    #pragma unroll
    for (int o = 16; o; o >>= 1) ss += __shfl_xor_sync(~0u, ss, o);
    if ((tid & 31) == 0) s4[tid >> 5] = ss;
    __syncthreads();
    ss = s4[0] + s4[1] + s4[2] + s4[3];
    if (tid == 0) g_fn2[pb] = ss;
    float inv = 1.0f / fmaxf(sqrtf(ss), 1e-12f);
    ((float4*)(g_img + (size_t)pb * DD))[tid] =
        make_float4(f.x*inv, f.y*inv, f.z*inv, f.w*inv);
    __syncthreads();

    float4 t = ((const float4*)(text + ((size_t)b * PP + p) * DD))[tid];
    float ts = t.x*t.x + t.y*t.y + t.z*t.z + t.w*t.w;
    #pragma unroll
    for (int o = 16; o; o >>= 1) ts += __shfl_xor_sync(~0u, ts, o);
    if ((tid & 31) == 0) s4[tid >> 5] = ts;
    __syncthreads();
    ts = s4[0] + s4[1] + s4[2] + s4[3];
    float tinv = 1.0f / fmaxf(sqrtf(ts), 1e-12f);
    ((float4*)(g_txt + (size_t)pb * DD))[tid] =
        make_float4(t.x*tinv, t.y*tinv, t.z*tinv, t.w*tinv);
}

// ================= neg term: bf16 mma.sync GEMM =================
// Block (n0 = bx*128, p = by): D[128 b][128 n], bf16 in / f32 acc, m16n8k16,
// 8 warps, warp tile 64x32. K=512 in 16 chunks of 32.
// A: bf16 via cp.async, 3 stages. B: fp32 via cp.async (2 stages) ->
// per-iter cvt phase (smem->reg->smem bf16, 2 stages) + exact fp32 cn2.
#define APITCH 80                  // bf16 rows: 40 bf16, conflict-free frags
#define A_STAGE 10240              // 128*80
#define BFPITCH 144                // fp32 staging rows: 36 floats
#define BF_STAGE 18432             // 128*144
#define B16_STAGE 10240
#define OFF_BF 30720               // 3*A_STAGE
#define OFF_B16 67584              // OFF_BF + 2*BF_STAGE
#define NEG_SMEM 88064             // OFF_B16 + 2*B16_STAGE

__device__ __forceinline__ void load_A(const __nv_bfloat16* __restrict__ Abf,
                                       uint32_t base, int c, int stage, int tid) {
    int k0 = c * 32;
    uint32_t sA = base + (uint32_t)stage * A_STAGE;
    #pragma unroll
    for (int i = 0; i < 2; i++) {
        int q = i * 256 + tid;            // 512 granules of 16B
        int row = q >> 2, g = q & 3;
        cp16(sA + (uint32_t)(row * APITCH + g * 16), Abf + (size_t)row * DD + k0 + g * 8);
    }
}
__device__ __forceinline__ void load_Bf(const float* __restrict__ B,
                                        uint32_t base, int c, int stage, int tid) {
    int k0 = c * 32;
    uint32_t sB = base + OFF_BF + (uint32_t)stage * BF_STAGE;
    #pragma unroll
    for (int i = 0; i < 4; i++) {
        int q = i * 256 + tid;            // 1024 granules of 16B
        int row = q >> 3, g = q & 7;
        cp16(sB + (uint32_t)(row * BFPITCH + g * 16), B + (size_t)row * DD + k0 + g * 4);
    }
}
// convert fp32 chunk c (smem stage c&1) -> bf16 stage c&1; returns cn2 partial
// thread map: r = tid&127 (row), h = tid>>7 (k-half). Conflict-free LDS/STS.
__device__ __forceinline__ float cvt_chunk(const char* dsm, uint32_t base, int c, int tid) {
    int r = tid & 127, h = tid >> 7;
    const float4* src = (const float4*)(dsm + OFF_BF + (size_t)(c & 1) * BF_STAGE
                                        + r * BFPITCH + h * 64);
    uint32_t u[8];
    float cn2 = 0.0f;
    #pragma unroll
    for (int i = 0; i < 4; i++) {
        float4 v = src[i];
        cn2 += v.x*v.x + v.y*v.y + v.z*v.z + v.w*v.w;
        u[2*i]   = pack_bf16(v.x, v.y);
        u[2*i+1] = pack_bf16(v.z, v.w);
    }
    uint32_t dst = base + OFF_B16 + (uint32_t)((c & 1) * B16_STAGE)
                 + (uint32_t)(r * APITCH + ((h ^ (r & 1)) * 32));
    sts128(dst, u[0], u[1], u[2], u[3]);
    sts128(dst + 16, u[4], u[5], u[6], u[7]);
    return cn2;
}

__global__ void __launch_bounds__(256, 2)
k_neg(const float* __restrict__ centers) {
    extern __shared__ __align__(16) char dsm[];
    __shared__ float s_part[256];
    __shared__ float s_cn2[128];
    __shared__ float s_fn2[128];
    __shared__ float s_keep[128];
    __shared__ float s_bsum[128];

    uint32_t base = smem_u32(dsm);
    int tid = threadIdx.x;
    int wid = tid >> 5, lane = tid & 31;
    int row4 = lane >> 2, col4 = lane & 3;
    int warp_m = wid >> 2, warp_n = wid & 3;
    int mbase = warp_m * 64, nbase = warp_n * 32;
    int p = blockIdx.y;
    int n0 = blockIdx.x * 128;

    if (tid < 128) {
        s_keep[tid] = 1.0f - g_negmask[n0 + tid];
        s_fn2[tid] = g_fn2[p * BB + tid];
        s_bsum[tid] = 0.0f;
    }

    const __nv_bfloat16* Abf = g_featbf + (size_t)p * BB * DD;
    const float* B = centers + ((size_t)p * NN + n0) * DD;

    float acc[4][4][4];
    #pragma unroll
    for (int i = 0; i < 4; i++)
        #pragma unroll
        for (int j = 0; j < 4; j++)
            #pragma unroll
            for (int r = 0; r < 4; r++) acc[i][j][r] = 0.0f;
    float cn2acc = 0.0f;

    // ---- prologue: G0, G1; convert chunk 0 ----
    load_A(Abf, base, 0, 0, tid); load_Bf(B, base, 0, 0, tid); CP_COMMIT();
    load_A(Abf, base, 1, 1, tid); load_Bf(B, base, 1, 1, tid); CP_COMMIT();
    CP_WAIT1();                     // G0 complete
    __syncthreads();
    cn2acc += cvt_chunk(dsm, base, 0, tid);

    for (int c = 0; c < 16; c++) {
        CP_WAIT0();                 // G_{c+1} complete (A(c+1), Bf(c+1))
        __syncthreads();            // cvt STS of chunk c visible; WAR stages drained

        if (c + 2 < 16) {           // issue G_{c+2}
            load_A(Abf, base, c + 2, (c + 2) % 3, tid);
            load_Bf(B, base, c + 2, (c + 2) & 1, tid);
            CP_COMMIT();
        }
        if (c + 1 < 16)             // convert chunk c+1 (fp32 smem -> bf16 smem)
            cn2acc += cvt_chunk(dsm, base, c + 1, tid);

        const char* sA = dsm + (size_t)(c % 3) * A_STAGE;
        const char* sB = dsm + OFF_B16 + (size_t)(c & 1) * B16_STAGE;

        #pragma unroll
        for (int kk = 0; kk < 2; kk++) {
            uint32_t afr[4][4];
            #pragma unroll
            for (int i = 0; i < 4; i++) {
                int row = mbase + i * 16 + row4;
                const char* Ar = sA + row * APITCH + kk * 32 + col4 * 4;
                afr[i][0] = *(const uint32_t*)(Ar);
                afr[i][1] = *(const uint32_t*)(Ar + 8 * APITCH);
                afr[i][2] = *(const uint32_t*)(Ar + 16);
                afr[i][3] = *(const uint32_t*)(Ar + 8 * APITCH + 16);
            }
            uint32_t bfr[4][2];
            #pragma unroll
            for (int j = 0; j < 4; j++) {
                int n = nbase + j * 8 + row4;
                const char* Br = sB + n * APITCH + ((kk ^ (n & 1)) * 32) + col4 * 4;
                bfr[j][0] = *(const uint32_t*)(Br);
                bfr[j][1] = *(const uint32_t*)(Br + 16);
            }
            #pragma unroll
            for (int i = 0; i < 4; i++)
                #pragma unroll
                for (int j = 0; j < 4; j++)
                    mma_bf16(acc[i][j], afr[i], bfr[j]);
        }
    }

    // cn2: combine the two k-half partials per row (exact fp32)
    s_part[tid] = cn2acc;
    __syncthreads();
    if (tid < 128) s_cn2[tid] = s_part[tid] + s_part[tid + 128];
    __syncthreads();

    #pragma unroll
    for (int i = 0; i < 4; i++) {
        #pragma unroll
        for (int half = 0; half < 2; half++) {
            int b = mbase + i * 16 + row4 + half * 8;
            float fn2v = s_fn2[b];
            float s = 0.0f;
            #pragma unroll
            for (int j = 0; j < 4; j++) {
                #pragma unroll
                for (int q = 0; q < 2; q++) {
                    int n = nbase + j * 8 + col4 * 2 + q;
                    float v = acc[i][j][half * 2 + q];
                    float pd2 = fn2v + s_cn2[n] - 2.0f * v;
                    float dist = sqrtf(fmaxf(pd2, 1e-12f));
                    s += __expf(-SCALEC * dist) * s_keep[n];
                }
            }
            atomicAdd(&s_bsum[b], s);
        }
    }
    __syncthreads();
    if (tid < 128) atomicAdd(&g_negsum[p * BB + tid], s_bsum[tid]);
}

// ================= tail: pos + align + final (one launch) =================
__global__ void __launch_bounds__(256) k_tail(const float* __restrict__ feature,
                                              const float* __restrict__ centers,
                                              const int* __restrict__ cross,
                                              const int* __restrict__ vid,
                                              float* __restrict__ out) {
    int tid = threadIdx.x;
    int bid = blockIdx.x;

    if (bid < 512) {
        // -------- positive term for pb = bid (exact fp32) --------
        __shared__ __align__(16) float s_f[DD];
        __shared__ float s_e[KK];
        int pb = bid; int p = pb >> 7, b = pb & 127;
        if (tid < 128) ((float4*)s_f)[tid] = ((const float4*)(feature + (size_t)pb * DD))[tid];
        __syncthreads();
        int w = tid >> 5, lane = tid & 31;
        float fn2 = g_fn2[pb];
        for (int k = w; k < KK; k += 8) {
            int n = cross[b * KK + k];
            const float4* c4 = (const float4*)(centers + ((size_t)p * NN + n) * DD);
            float dot = 0.0f, cn2 = 0.0f;
            for (int i = lane; i < DD/4; i += 32) {
                float4 c = c4[i];
                float4 f = ((const float4*)s_f)[i];
                dot += f.x*c.x + f.y*c.y + f.z*c.z + f.w*c.w;
                cn2 += c.x*c.x + c.y*c.y + c.z*c.z + c.w*c.w;
            }
            #pragma unroll
            for (int o = 16; o; o >>= 1) {
                dot += __shfl_xor_sync(~0u, dot, o);
                cn2 += __shfl_xor_sync(~0u, cn2, o);
            }
            if (lane == 0) {
                float dist = sqrtf(fmaxf(fn2 + cn2 - 2.0f * dot, 1e-12f));
                s_e[k] = expf(-SCALEC * dist);
            }
        }
        __syncthreads();
        if (tid == 0) {
            float se = 0.0f;
            for (int k = 0; k < KK; k++) se += s_e[k];
            atomicAdd(&g_lp[p], logf(g_negsum[pb]) - logf(se));
        }
    } else {
        // -------- align tile: colm/valid provably all-true (diag cos/TEMP = 2 > 0.7) --------
        __shared__ __align__(16) float rows[8][512];
        __shared__ __align__(16) float chunk[128][36];
        __shared__ __align__(16) float sim[2][8][128];
        int ab = bid - 512;
        int p = ab >> 4;
        int r0 = (ab & 15) * 8;
        int c = tid & 127, rh = tid >> 7;

        for (int src = 0; src < 2; src++) {
            const float* X = (src ? g_txt : g_img) + (size_t)p * BB * DD;
            __syncthreads();
            for (int i = tid; i < 8 * 128; i += 256) {
                int r = i >> 7, g = i & 127;
                ((float4*)rows[r])[g] = ((const float4*)(X + (size_t)(r0 + r) * DD))[g];
            }
            float acc[4] = {0.f, 0.f, 0.f, 0.f};
            for (int d0 = 0; d0 < 512; d0 += 32) {
                __syncthreads();
                for (int i = tid; i < 1024; i += 256) {
                    int r = i >> 3, g = i & 7;
                    float4 v = ((const float4*)(X + (size_t)r * DD + d0))[g];
                    chunk[r][g*4+0] = v.x; chunk[r][g*4+1] = v.y;
                    chunk[r][g*4+2] = v.z; chunk[r][g*4+3] = v.w;
                }
                __syncthreads();
                #pragma unroll
                for (int dg = 0; dg < 8; dg++) {
                    float4 cv = *(const float4*)&chunk[c][dg * 4];
                    #pragma unroll
                    for (int i = 0; i < 4; i++) {
                        float4 rv = *(const float4*)&rows[rh * 4 + i][d0 + dg * 4];
                        acc[i] += rv.x*cv.x + rv.y*cv.y + rv.z*cv.z + rv.w*cv.w;
                    }
                }
            }
            #pragma unroll
            for (int i = 0; i < 4; i++) sim[src][rh * 4 + i][c] = acc[i] * TEMP_INV;
        }
        __syncthreads();

        int w = tid >> 5, lane = tid & 31;
        float li[4], lt[4];
        #pragma unroll
        for (int j = 0; j < 4; j++) {
            li[j] = sim[0][w][lane + 32 * j];
            lt[j] = sim[1][w][lane + 32 * j];
        }
        float mi = fmaxf(fmaxf(li[0], li[1]), fmaxf(li[2], li[3]));
        float mt = fmaxf(fmaxf(lt[0], lt[1]), fmaxf(lt[2], lt[3]));
        #pragma unroll
        for (int o = 16; o; o >>= 1) {
            mi = fmaxf(mi, __shfl_xor_sync(~0u, mi, o));
            mt = fmaxf(mt, __shfl_xor_sync(~0u, mt, o));
        }
        float si = 0.f, stt = 0.f;
        #pragma unroll
        for (int j = 0; j < 4; j++) { si += expf(li[j] - mi); stt += expf(lt[j] - mt); }
        #pragma unroll
        for (int o = 16; o; o >>= 1) {
            si += __shfl_xor_sync(~0u, si, o);
            stt += __shfl_xor_sync(~0u, stt, o);
        }
        float Li = mi + logf(si), Lt = mt + logf(stt);
        float kl = 0.f;
        #pragma unroll
        for (int j = 0; j < 4; j++) {
            float lpi = li[j] - Li, lpt = lt[j] - Lt;
            kl += expf(lpt) * (lpt - lpi) + expf(lpi) * (lpi - lpt);
        }
        #pragma unroll
        for (int o = 16; o; o >>= 1) kl += __shfl_xor_sync(~0u, kl, o);
        if (lane == 0) atomicAdd(&g_klp[p], kl);
    }

    // -------- last-block-done: finalize --------
    __shared__ int s_last;
    __syncthreads();
    if (tid == 0) {
        __threadfence();
        s_last = (atomicAdd(&g_done, 1) == 575);
    }
    __syncthreads();
    if (s_last) {
        __threadfence();
        for (int i = tid; i < BB*KK; i += 256) out[3 + i] = (float)vid[__ldcg(&cross[i])];
        if (tid == 0) {
            float contr = 0.0f;
            for (int p = 0; p < PP; p++) {
                float lp = __ldcg(&g_lp[p]) / (float)BB;
                if (isnan(lp)) lp = 0.0f;
                contr += lp;
            }
            contr /= (float)PP;
            float align = 0.0f;
            for (int p = 0; p < PP; p++) align += 0.5f * __ldcg(&g_klp[p]) / (float)BB;
            out[0] = contr + KL_WEIGHT * align;
            out[1] = contr;
            out[2] = align;
        }
    }
}

// ================= launch =================
extern "C" void kernel_launch(void* const* d_in, const int* in_sizes, int n_in,
                              void* d_out, int out_size) {
    const float* feature = (const float*)d_in[0];
    const float* text    = (const float*)d_in[1];
    const float* centers = (const float*)d_in[2];
    const int*   positn  = (const int*)d_in[3];
    const int*   cross   = (const int*)d_in[4];
    const int*   vid     = (const int*)d_in[5];
    float* out = (float*)d_out;

    cudaFuncSetAttribute(k_neg, cudaFuncAttributeMaxDynamicSharedMemorySize, NEG_SMEM);

    void *pm, *ps, *pl, *pk, *pd;
    cudaGetSymbolAddress(&pm, g_negmask);
    cudaGetSymbolAddress(&ps, g_negsum);
    cudaGetSymbolAddress(&pl, g_lp);
    cudaGetSymbolAddress(&pk, g_klp);
    cudaGetSymbolAddress(&pd, g_done);
    cudaMemsetAsync(pm, 0, NN * sizeof(float));
    cudaMemsetAsync(ps, 0, PP * BB * sizeof(float));
    cudaMemsetAsync(pl, 0, PP * sizeof(float));
    cudaMemsetAsync(pk, 0, PP * sizeof(float));
    cudaMemsetAsync(pd, 0, sizeof(int));

    k_pre<<<513, 128>>>(feature, text, cross, positn);
    k_neg<<<dim3(NN/128, PP), 256, NEG_SMEM>>>(centers);
    k_tail<<<576, 256>>>(feature, centers, cross, vid, out);
}

// round 13
// speedup vs baseline: 1.2754x; 1.0863x over previous
#include <cuda_runtime.h>
#include <cuda_bf16.h>
#include <cstdint>
#include <math.h>

#define PP 4
#define BB 128
#define DD 512
#define NN 32768
#define KK 10
#define TEMP_INV 2.0f
#define SCALEC 10.0f
#define KL_WEIGHT (59.0f/120.0f)

// ================= scratch (16B-aligned: we float4-cast these) =================
__device__ __align__(16) float g_img[PP*BB*DD];
__device__ __align__(16) float g_txt[PP*BB*DD];
__device__ __align__(16) float g_fn2[PP*BB];
__device__ __align__(16) float g_negmask[NN];     // 0 = keep, 1 = masked
__device__ __align__(16) float g_negsum[PP*BB];
__device__ __align__(16) float g_lpk[2*PP];       // [0:PP)=lp, [PP:2PP)=klp (one memset)
__device__ __align__(16) __nv_bfloat16 g_featbf[PP*BB*DD];
__device__ int g_done;

// ================= helpers =================
__device__ __forceinline__ void cp16(uint32_t dst, const void* src) {
    asm volatile("cp.async.cg.shared.global [%0], [%1], 16;" :: "r"(dst), "l"(src));
}
#define CP_COMMIT() asm volatile("cp.async.commit_group;" ::: "memory")
#define CP_WAITG(n) asm volatile("cp.async.wait_group %0;" :: "n"(n) : "memory")

__device__ __forceinline__ uint32_t smem_u32(const void* p) {
    uint32_t a;
    asm("{ .reg .u64 t; cvta.to.shared.u64 t, %1; cvt.u32.u64 %0, t; }" : "=r"(a) : "l"(p));
    return a;
}
__device__ __forceinline__ uint32_t pack_bf16(float lo, float hi) {
    uint32_t u;
    asm("cvt.rn.bf16x2.f32 %0, %1, %2;" : "=r"(u) : "f"(hi), "f"(lo));
    return u;
}
__device__ __forceinline__ void sts128(uint32_t addr, uint32_t a, uint32_t b,
                                       uint32_t c, uint32_t d) {
    asm volatile("st.shared.v4.b32 [%0], {%1,%2,%3,%4};"
                 :: "r"(addr), "r"(a), "r"(b), "r"(c), "r"(d));
}
#define LDSM_X4(r0, r1, r2, r3, addr) \
    asm volatile("ldmatrix.sync.aligned.m8n8.x4.shared.b16 {%0,%1,%2,%3}, [%4];" \
                 : "=r"(r0), "=r"(r1), "=r"(r2), "=r"(r3) : "r"(addr))
__device__ __forceinline__ void mma_bf16(float* d, const uint32_t* a, const uint32_t* b) {
    asm volatile(
        "mma.sync.aligned.m16n8k16.row.col.f32.bf16.bf16.f32 "
        "{%0,%1,%2,%3}, {%4,%5,%6,%7}, {%8,%9}, {%0,%1,%2,%3};"
        : "+f"(d[0]), "+f"(d[1]), "+f"(d[2]), "+f"(d[3])
        : "r"(a[0]), "r"(a[1]), "r"(a[2]), "r"(a[3]), "r"(b[0]), "r"(b[1]));
}

// ================= kernel A: scatter + normalize + bf16 feature =================
__global__ void __launch_bounds__(128) k_pre(const float* __restrict__ feature,
                                             const float* __restrict__ text,
                                             const int* __restrict__ cross,
                                             const int* __restrict__ pos) {
    int tid = threadIdx.x;
    if (blockIdx.x == 0) {
        for (int i = tid; i < BB*KK; i += 128) g_negmask[cross[i]] = 1.0f;
        for (int i = tid; i < BB; i += 128) g_negmask[pos[i]] = 1.0f;
        return;
    }
    __shared__ float s4[4];
    int pb = blockIdx.x - 1;
    int p = pb >> 7, b = pb & 127;

    float4 f = ((const float4*)(feature + (size_t)pb * DD))[tid];
    ((uint2*)(g_featbf + (size_t)pb * DD))[tid] =
        make_uint2(pack_bf16(f.x, f.y), pack_bf16(f.z, f.w));
    float ss = f.x*f.x + f.y*f.y + f.z*f.z + f.w*f.w;
    #pragma unroll
    for (int o = 16; o; o >>= 1) ss += __shfl_xor_sync(~0u, ss, o);
    if ((tid & 31) == 0) s4[tid >> 5] = ss;
    __syncthreads();
    ss = s4[0] + s4[1] + s4[2] + s4[3];
    if (tid == 0) g_fn2[pb] = ss;
    float inv = 1.0f / fmaxf(sqrtf(ss), 1e-12f);
    ((float4*)(g_img + (size_t)pb * DD))[tid] =
        make_float4(f.x*inv, f.y*inv, f.z*inv, f.w*inv);
    __syncthreads();

    float4 t = ((const float4*)(text + ((size_t)b * PP + p) * DD))[tid];
    float ts = t.x*t.x + t.y*t.y + t.z*t.z + t.w*t.w;
    #pragma unroll
    for (int o = 16; o; o >>= 1) ts += __shfl_xor_sync(~0u, ts, o);
    if ((tid & 31) == 0) s4[tid >> 5] = ts;
    __syncthreads();
    ts = s4[0] + s4[1] + s4[2] + s4[3];
    float tinv = 1.0f / fmaxf(sqrtf(ts), 1e-12f);
    ((float4*)(g_txt + (size_t)pb * DD))[tid] =
        make_float4(t.x*tinv, t.y*tinv, t.z*tinv, t.w*tinv);
}

// ================= neg term: bf16 mma.sync GEMM =================
// Block (n0 = bx*128, p = by): D[128 b][128 n], bf16 in / f32 acc, m16n8k16,
// 8 warps, warp tile 64x32. K=512 in 16 chunks of 32.
// Pipeline: 3 cp.async groups in flight (2-body slack). A: bf16, 4 stages.
// Bf: fp32 staging, pitch 128 + granule-XOR swizzle, 3 stages. B16: 2 stages.
// Fragments via ldmatrix.x4.
#define APITCH 80
#define A_STAGE 10240              // 128*80
#define BF_STAGE 16384             // 128*128
#define B16_STAGE 10240
#define OFF_BF 40960               // 4*A_STAGE
#define OFF_B16 90112              // OFF_BF + 3*BF_STAGE
#define NEG_SMEM 110592            // OFF_B16 + 2*B16_STAGE

__device__ __forceinline__ void load_A(const __nv_bfloat16* __restrict__ Abf,
                                       uint32_t base, int c, int stage, int tid) {
    int k0 = c * 32;
    uint32_t sA = base + (uint32_t)stage * A_STAGE;
    #pragma unroll
    for (int i = 0; i < 2; i++) {
        int q = i * 256 + tid;
        int row = q >> 2, g = q & 3;
        cp16(sA + (uint32_t)(row * APITCH + g * 16), Abf + (size_t)row * DD + k0 + g * 8);
    }
}
__device__ __forceinline__ void load_Bf(const float* __restrict__ B,
                                        uint32_t base, int c, int stage, int tid) {
    int k0 = c * 32;
    uint32_t sB = base + OFF_BF + (uint32_t)stage * BF_STAGE;
    #pragma unroll
    for (int i = 0; i < 4; i++) {
        int q = i * 256 + tid;
        int row = q >> 3, g = q & 7;
        cp16(sB + (uint32_t)(row * 128 + ((g ^ (row & 7)) * 16)),
             B + (size_t)row * DD + k0 + g * 4);
    }
}
// convert fp32 chunk c (Bf stage c%3) -> bf16 stage c&1; returns cn2 partial
__device__ __forceinline__ float cvt_chunk(const char* dsm, uint32_t base, int c, int tid) {
    int r = tid & 127, h = tid >> 7;
    const char* srcb = dsm + OFF_BF + (size_t)(c % 3) * BF_STAGE + r * 128;
    uint32_t u[8];
    float cn2 = 0.0f;
    #pragma unroll
    for (int i = 0; i < 4; i++) {
        int g = h * 4 + i;
        float4 v = *(const float4*)(srcb + ((g ^ (r & 7)) * 16));
        cn2 += v.x*v.x + v.y*v.y + v.z*v.z + v.w*v.w;
        u[2*i]   = pack_bf16(v.x, v.y);
        u[2*i+1] = pack_bf16(v.z, v.w);
    }
    uint32_t dst = base + OFF_B16 + (uint32_t)((c & 1) * B16_STAGE)
                 + (uint32_t)(r * APITCH + ((h ^ (r & 1)) * 32));
    sts128(dst, u[0], u[1], u[2], u[3]);
    sts128(dst + 16, u[4], u[5], u[6], u[7]);
    return cn2;
}

__global__ void __launch_bounds__(256, 2)
k_neg(const float* __restrict__ centers) {
    extern __shared__ __align__(16) char dsm[];
    uint32_t base = smem_u32(dsm);
    int tid = threadIdx.x;
    int wid = tid >> 5, lane = tid & 31;
    int row4 = lane >> 2, col4 = lane & 3;
    int warp_m = wid >> 2, warp_n = wid & 3;
    int mbase = warp_m * 64, nbase = warp_n * 32;
    int p = blockIdx.y;
    int n0 = blockIdx.x * 128;

    const __nv_bfloat16* Abf = g_featbf + (size_t)p * BB * DD;
    const float* B = centers + ((size_t)p * NN + n0) * DD;

    // ldmatrix per-lane offsets
    int lr = lane & 7, lm1 = (lane >> 3) & 1, lm2 = lane >> 4;
    uint32_t aoff = (uint32_t)((mbase + lr + lm1 * 8) * APITCH + lm2 * 16);
    int nB = nbase + lm2 * 8 + lr;
    uint32_t boff = (uint32_t)(nB * APITCH + lm1 * 16);
    uint32_t bsw = (uint32_t)((lane & 1) * 32);

    float acc[4][4][4];
    #pragma unroll
    for (int i = 0; i < 4; i++)
        #pragma unroll
        for (int j = 0; j < 4; j++)
            #pragma unroll
            for (int r = 0; r < 4; r++) acc[i][j][r] = 0.0f;
    float cn2acc = 0.0f;

    // ---- prologue: 3 groups in flight ----
    #pragma unroll
    for (int g = 0; g < 3; g++) {
        load_A(Abf, base, g, g, tid);
        load_Bf(B, base, g, g, tid);
        CP_COMMIT();
    }
    CP_WAITG(2);                    // G0 done
    __syncthreads();
    cn2acc += cvt_chunk(dsm, base, 0, tid);

    for (int c = 0; c < 16; c++) {
        CP_WAITG(1);                // G_{c+1} done (2 bodies of slack on G_{c+2..3})
        __syncthreads();

        if (c + 3 < 16) {
            load_A(Abf, base, c + 3, (c + 3) & 3, tid);
            load_Bf(B, base, c + 3, (c + 3) % 3, tid);
        }
        CP_COMMIT();                // uniform 1 group/iter (empty near tail)

        if (c + 1 < 16)
            cn2acc += cvt_chunk(dsm, base, c + 1, tid);

        uint32_t sA = base + (uint32_t)((c & 3) * A_STAGE);
        uint32_t sB = base + OFF_B16 + (uint32_t)((c & 1) * B16_STAGE);

        #pragma unroll
        for (int kk = 0; kk < 2; kk++) {
            uint32_t afr[4][4];
            #pragma unroll
            for (int i = 0; i < 4; i++)
                LDSM_X4(afr[i][0], afr[i][1], afr[i][2], afr[i][3],
                        sA + aoff + (uint32_t)(i * 16 * APITCH + kk * 32));
            uint32_t bfr[4][2];
            LDSM_X4(bfr[0][0], bfr[0][1], bfr[1][0], bfr[1][1],
                    sB + boff + ((uint32_t)(kk * 32) ^ bsw));
            LDSM_X4(bfr[2][0], bfr[2][1], bfr[3][0], bfr[3][1],
                    sB + boff + (uint32_t)(16 * APITCH) + ((uint32_t)(kk * 32) ^ bsw));
            #pragma unroll
            for (int i = 0; i < 4; i++)
                #pragma unroll
                for (int j = 0; j < 4; j++)
                    mma_bf16(acc[i][j], afr[i], bfr[j]);
        }
    }

    // ---- epilogue: scratch lives in freed pipeline smem ----
    __syncthreads();                      // all frag reads done
    float* sc = (float*)dsm;
    sc[tid] = cn2acc;
    __syncthreads();
    float* s_cn2  = sc + 256;
    float* s_fn2  = sc + 384;
    float* s_keep = sc + 512;
    float* s_bsum = sc + 640;
    if (tid < 128) {
        s_cn2[tid] = sc[tid] + sc[tid + 128];
        s_fn2[tid] = g_fn2[p * BB + tid];
        s_keep[tid] = 1.0f - g_negmask[n0 + tid];
        s_bsum[tid] = 0.0f;
    }
    __syncthreads();

    #pragma unroll
    for (int i = 0; i < 4; i++) {
        #pragma unroll
        for (int half = 0; half < 2; half++) {
            int b = mbase + i * 16 + row4 + half * 8;
            float fn2v = s_fn2[b];
            float s = 0.0f;
            #pragma unroll
            for (int j = 0; j < 4; j++) {
                #pragma unroll
                for (int q = 0; q < 2; q++) {
                    int n = nbase + j * 8 + col4 * 2 + q;
                    float v = acc[i][j][half * 2 + q];
                    float pd2 = fn2v + s_cn2[n] - 2.0f * v;
                    float dist = sqrtf(fmaxf(pd2, 1e-12f));
                    s += __expf(-SCALEC * dist) * s_keep[n];
                }
            }
            atomicAdd(&s_bsum[b], s);
        }
    }
    __syncthreads();
    if (tid < 128) atomicAdd(&g_negsum[p * BB + tid], s_bsum[tid]);
}

// ================= tail: pos + align + final (one launch) =================
__global__ void __launch_bounds__(256) k_tail(const float* __restrict__ feature,
                                              const float* __restrict__ centers,
                                              const int* __restrict__ cross,
                                              const int* __restrict__ vid,
                                              float* __restrict__ out) {
    int tid = threadIdx.x;
    int bid = blockIdx.x;

    if (bid < 512) {
        // -------- positive term for pb = bid (exact fp32) --------
        __shared__ __align__(16) float s_f[DD];
        __shared__ float s_e[KK];
        int pb = bid; int p = pb >> 7, b = pb & 127;
        if (tid < 128) ((float4*)s_f)[tid] = ((const float4*)(feature + (size_t)pb * DD))[tid];
        __syncthreads();
        int w = tid >> 5, lane = tid & 31;
        float fn2 = g_fn2[pb];
        for (int k = w; k < KK; k += 8) {
            int n = cross[b * KK + k];
            const float4* c4 = (const float4*)(centers + ((size_t)p * NN + n) * DD);
            float dot = 0.0f, cn2 = 0.0f;
            for (int i = lane; i < DD/4; i += 32) {
                float4 c = c4[i];
                float4 f = ((const float4*)s_f)[i];
                dot += f.x*c.x + f.y*c.y + f.z*c.z + f.w*c.w;
                cn2 += c.x*c.x + c.y*c.y + c.z*c.z + c.w*c.w;
            }
            #pragma unroll
            for (int o = 16; o; o >>= 1) {
                dot += __shfl_xor_sync(~0u, dot, o);
                cn2 += __shfl_xor_sync(~0u, cn2, o);
            }
            if (lane == 0) {
                float dist = sqrtf(fmaxf(fn2 + cn2 - 2.0f * dot, 1e-12f));
                s_e[k] = expf(-SCALEC * dist);
            }
        }
        __syncthreads();
        if (tid == 0) {
            float se = 0.0f;
            for (int k = 0; k < KK; k++) se += s_e[k];
            atomicAdd(&g_lpk[p], logf(g_negsum[pb]) - logf(se));
        }
    } else {
        // -------- align tile: colm/valid provably all-true (diag cos/TEMP = 2 > 0.7) --------
        __shared__ __align__(16) float rows[8][512];
        __shared__ __align__(16) float chunk[128][36];
        __shared__ __align__(16) float sim[2][8][128];
        int ab = bid - 512;
        int p = ab >> 4;
        int r0 = (ab & 15) * 8;
        int c = tid & 127, rh = tid >> 7;

        for (int src = 0; src < 2; src++) {
            const float* X = (src ? g_txt : g_img) + (size_t)p * BB * DD;
            __syncthreads();
            for (int i = tid; i < 8 * 128; i += 256) {
                int r = i >> 7, g = i & 127;
                ((float4*)rows[r])[g] = ((const float4*)(X + (size_t)(r0 + r) * DD))[g];
            }
            float acc[4] = {0.f, 0.f, 0.f, 0.f};
            for (int d0 = 0; d0 < 512; d0 += 32) {
                __syncthreads();
                for (int i = tid; i < 1024; i += 256) {
                    int r = i >> 3, g = i & 7;
                    float4 v = ((const float4*)(X + (size_t)r * DD + d0))[g];
                    chunk[r][g*4+0] = v.x; chunk[r][g*4+1] = v.y;
                    chunk[r][g*4+2] = v.z; chunk[r][g*4+3] = v.w;
                }
                __syncthreads();
                #pragma unroll
                for (int dg = 0; dg < 8; dg++) {
                    float4 cv = *(const float4*)&chunk[c][dg * 4];
                    #pragma unroll
                    for (int i = 0; i < 4; i++) {
                        float4 rv = *(const float4*)&rows[rh * 4 + i][d0 + dg * 4];
                        acc[i] += rv.x*cv.x + rv.y*cv.y + rv.z*cv.z + rv.w*cv.w;
                    }
                }
            }
            #pragma unroll
            for (int i = 0; i < 4; i++) sim[src][rh * 4 + i][c] = acc[i] * TEMP_INV;
        }
        __syncthreads();

        int w = tid >> 5, lane = tid & 31;
        float li[4], lt[4];
        #pragma unroll
        for (int j = 0; j < 4; j++) {
            li[j] = sim[0][w][lane + 32 * j];
            lt[j] = sim[1][w][lane + 32 * j];
        }
        float mi = fmaxf(fmaxf(li[0], li[1]), fmaxf(li[2], li[3]));
        float mt = fmaxf(fmaxf(lt[0], lt[1]), fmaxf(lt[2], lt[3]));
        #pragma unroll
        for (int o = 16; o; o >>= 1) {
            mi = fmaxf(mi, __shfl_xor_sync(~0u, mi, o));
            mt = fmaxf(mt, __shfl_xor_sync(~0u, mt, o));
        }
        float si = 0.f, stt = 0.f;
        #pragma unroll
        for (int j = 0; j < 4; j++) { si += expf(li[j] - mi); stt += expf(lt[j] - mt); }
        #pragma unroll
        for (int o = 16; o; o >>= 1) {
            si += __shfl_xor_sync(~0u, si, o);
            stt += __shfl_xor_sync(~0u, stt, o);
        }
        float Li = mi + logf(si), Lt = mt + logf(stt);
        float kl = 0.f;
        #pragma unroll
        for (int j = 0; j < 4; j++) {
            float lpi = li[j] - Li, lpt = lt[j] - Lt;
            kl += expf(lpt) * (lpt - lpi) + expf(lpi) * (lpi - lpt);
        }
        #pragma unroll
        for (int o = 16; o; o >>= 1) kl += __shfl_xor_sync(~0u, kl, o);
        if (lane == 0) atomicAdd(&g_lpk[PP + p], kl);
    }

    // -------- last-block-done: finalize --------
    __shared__ int s_last;
    __syncthreads();
    if (tid == 0) {
        __threadfence();
        s_last = (atomicAdd(&g_done, 1) == 575);
    }
    __syncthreads();
    if (s_last) {
        __threadfence();
        for (int i = tid; i < BB*KK; i += 256) out[3 + i] = (float)vid[__ldcg(&cross[i])];
        if (tid == 0) {
            float contr = 0.0f;
            for (int p = 0; p < PP; p++) {
                float lp = __ldcg(&g_lpk[p]) / (float)BB;
                if (isnan(lp)) lp = 0.0f;
                contr += lp;
            }
            contr /= (float)PP;
            float align = 0.0f;
            for (int p = 0; p < PP; p++) align += 0.5f * __ldcg(&g_lpk[PP + p]) / (float)BB;
            out[0] = contr + KL_WEIGHT * align;
            out[1] = contr;
            out[2] = align;
        }
    }
}

// ================= launch =================
extern "C" void kernel_launch(void* const* d_in, const int* in_sizes, int n_in,
                              void* d_out, int out_size) {
    const float* feature = (const float*)d_in[0];
    const float* text    = (const float*)d_in[1];
    const float* centers = (const float*)d_in[2];
    const int*   positn  = (const int*)d_in[3];
    const int*   cross   = (const int*)d_in[4];
    const int*   vid     = (const int*)d_in[5];
    float* out = (float*)d_out;

    cudaFuncSetAttribute(k_neg, cudaFuncAttributeMaxDynamicSharedMemorySize, NEG_SMEM);

    void *pm, *ps, *pl, *pd;
    cudaGetSymbolAddress(&pm, g_negmask);
    cudaGetSymbolAddress(&ps, g_negsum);
    cudaGetSymbolAddress(&pl, g_lpk);
    cudaGetSymbolAddress(&pd, g_done);
    cudaMemsetAsync(pm, 0, NN * sizeof(float));
    cudaMemsetAsync(ps, 0, PP * BB * sizeof(float));
    cudaMemsetAsync(pl, 0, 2 * PP * sizeof(float));
    cudaMemsetAsync(pd, 0, sizeof(int));

    k_pre<<<513, 128>>>(feature, text, cross, positn);
    k_neg<<<dim3(NN/128, PP), 256, NEG_SMEM>>>(centers);
    k_tail<<<576, 256>>>(feature, centers, cross, vid, out);
}